// round 14
// baseline (speedup 1.0000x reference)
#include <cuda_runtime.h>
#include <math.h>
#include <stdint.h>

#define BATCH 8
#define CI    256
#define CO    256
#define H     64
#define W     64
#define HW    4096
#define M_TOT 32768          // BATCH*HW
#define KDIM  2304           // CI*9
#define EPSV  1e-5f

// ---------------- scratch (__device__ globals: allocation-free rule) -------
__device__ float  g_valA[(size_t)M_TOT * KDIM]; // [m][k perm8], tf32-rounded (302 MB)
__device__ float  g_xT[(size_t)BATCH * HW * CI];// x transposed: [b][pix][ci] (134 MB)
__device__ float  g_om[108 * M_TOT];            // offset-conv partials [chunk*27+oc][m]
__device__ float4 g_par[BATCH * 9 * HW];        // (py, px, mask, -) per (b,kk,pixel)
__device__ float  g_wB[CO * KDIM];              // [co][k perm8], w*bn_scale, tf32-rounded

// k-permutation within 8-blocks: layout [k0,k4,k1,k5,k2,k6,k3,k7]
__device__ __forceinline__ int p8inv(int p) {
    return (p & ~7) + ((p & 7) >> 1) + ((p & 1) << 2);
}

// ===================== small helpers ========================================
__device__ __forceinline__ uint32_t smem_u32(const void* p) {
    uint32_t a;
    asm("{ .reg .u64 t; cvta.to.shared.u64 t, %1; cvt.u32.u64 %0, t; }" : "=r"(a) : "l"(p));
    return a;
}
__device__ __forceinline__ float tf32_rna(float v) {
    uint32_t u;
    asm("cvt.rna.tf32.f32 %0, %1;" : "=r"(u) : "f"(v));
    return __uint_as_float(u);
}
__device__ __forceinline__ void cp_async16(uint32_t dst, const void* src) {
    asm volatile("cp.async.cg.shared.global [%0], [%1], 16;" :: "r"(dst), "l"(src) : "memory");
}
#define CP_COMMIT() asm volatile("cp.async.commit_group;" ::: "memory")
#define CP_WAIT3()  asm volatile("cp.async.wait_group 3;" ::: "memory")

__device__ __forceinline__ void mma_tf32(float& c0, float& c1, float& c2, float& c3,
                                         uint32_t a0, uint32_t a1, uint32_t a2, uint32_t a3,
                                         uint32_t b0, uint32_t b1) {
    asm volatile(
        "mma.sync.aligned.m16n8k8.row.col.f32.tf32.tf32.f32 "
        "{%0,%1,%2,%3}, {%4,%5,%6,%7}, {%8,%9}, {%0,%1,%2,%3};"
        : "+f"(c0), "+f"(c1), "+f"(c2), "+f"(c3)
        : "r"(a0), "r"(a1), "r"(a2), "r"(a3), "r"(b0), "r"(b1));
}

// ============ Phase T: NCHW -> NHWC transpose (x -> g_xT) ===================
__global__ __launch_bounds__(256) void transpose_kernel(const float* __restrict__ x)
{
    __shared__ float s[32][33];
    int b    = blockIdx.z;
    int ci0  = blockIdx.y << 5;
    int pix0 = blockIdx.x << 5;
    int tid = threadIdx.x;
    int r = tid >> 5, c = tid & 31;

    const float* xb = x + (size_t)b * CI * HW;
#pragma unroll
    for (int rr = 0; rr < 4; rr++) {
        int ci = ci0 + r + (rr << 3);
        s[r + (rr << 3)][c] = xb[(size_t)ci * HW + pix0 + c];
    }
    __syncthreads();
    float* xT = g_xT + (size_t)b * HW * CI;
#pragma unroll
    for (int rr = 0; rr < 4; rr++) {
        int pix = pix0 + r + (rr << 3);
        xT[(size_t)pix * CI + ci0 + c] = s[c][r + (rr << 3)];
    }
}

// ============ Phase A1: offset conv partials (4-way ci split) ===============
__global__ __launch_bounds__(256) void offset_kernel(
    const float* __restrict__ x, const float* __restrict__ w_off)
{
    __shared__ float  xs[18 * 18];
    __shared__ float4 ws4[81];                 // [27][12] padded weights
    float* ws = (float*)ws4;

    int b     = blockIdx.y;
    int chunk = blockIdx.z;                    // ci chunk of 64
    int tile  = blockIdx.x;                    // 16 tiles of 16x16
    int h0 = (tile >> 2) << 4;
    int w0 = (tile & 3) << 4;
    int tid = threadIdx.x;
    int ty = tid >> 4, tx = tid & 15;
    int h = h0 + ty, ww = w0 + tx;

    float acc[27];
#pragma unroll
    for (int i = 0; i < 27; i++) acc[i] = 0.f;

    const float* xb = x + b * (CI * HW);
    int ci0 = chunk << 6;
    for (int cit = 0; cit < 64; cit++) {
        int ci = ci0 + cit;
        __syncthreads();
        for (int i = tid; i < 324; i += 256) {
            int r = i / 18, c = i - r * 18;
            int gy = h0 + r - 1, gx = w0 + c - 1;
            float v = 0.f;
            if (gy >= 0 && gy < H && gx >= 0 && gx < W)
                v = xb[ci * HW + gy * W + gx];
            xs[i] = v;
        }
        for (int i = tid; i < 324; i += 256) {
            int oc = i / 12, j = i - oc * 12;
            ws[i] = (j < 9) ? w_off[oc * KDIM + ci * 9 + j] : 0.f;
        }
        __syncthreads();

        float xv[9];
#pragma unroll
        for (int ky = 0; ky < 3; ky++)
#pragma unroll
            for (int kx = 0; kx < 3; kx++)
                xv[ky * 3 + kx] = xs[(ty + ky) * 18 + tx + kx];

        const float4* w4 = (const float4*)ws;
#pragma unroll
        for (int oc = 0; oc < 27; oc++) {
            float4 a0 = w4[oc * 3 + 0], a1 = w4[oc * 3 + 1], a2 = w4[oc * 3 + 2];
            acc[oc] += xv[0] * a0.x + xv[1] * a0.y + xv[2] * a0.z + xv[3] * a0.w
                     + xv[4] * a1.x + xv[5] * a1.y + xv[6] * a1.z + xv[7] * a1.w
                     + xv[8] * a2.x;
        }
    }

    int m = b * HW + h * W + ww;
#pragma unroll
    for (int oc = 0; oc < 27; oc++)
        g_om[(chunk * 27 + oc) * M_TOT + m] = acc[oc];
}

// ============ Phase A2: reduce partials -> bilinear params ==================
__global__ __launch_bounds__(256) void reduce_kernel(const float* __restrict__ b_off)
{
    int m = blockIdx.x * 256 + threadIdx.x;
    int b = m >> 12, pix = m & 4095;
    int h = pix >> 6, ww = pix & 63;

    float om[27];
#pragma unroll
    for (int oc = 0; oc < 27; oc++) {
        float s = b_off[oc];
#pragma unroll
        for (int c = 0; c < 4; c++)
            s += g_om[(c * 27 + oc) * M_TOT + m];
        om[oc] = s;
    }
#pragma unroll
    for (int kk = 0; kk < 9; kk++) {
        float msk = 1.f / (1.f + __expf(-om[18 + kk]));
        float py = (float)(h  + (kk / 3) - 1) + om[kk];
        float px = (float)(ww + (kk % 3) - 1) + om[9 + kk];
        g_par[(b * 9 + kk) * HW + pix] = make_float4(py, px, msk, 0.f);
    }
}

// ======= Phase W: scaled weights, perm8-laid-out =============================
__global__ void wt_kernel(const float* __restrict__ w,
                          const float* __restrict__ gamma,
                          const float* __restrict__ var)
{
    int co = blockIdx.x;
    float alpha = gamma[co] * rsqrtf(var[co] + EPSV);
    for (int k = threadIdx.x; k < KDIM; k += 256) {
        int pos = (k & ~7) + ((k & 3) << 1) + ((k & 7) >> 2);
        g_wB[co * KDIM + pos] = tf32_rna(w[co * KDIM + k] * alpha);
    }
}

// ============ Phase B: bilinear sampling (NHWC) -> g_valA[m][k perm8] =======
__global__ __launch_bounds__(256) void sample_kernel()
{
    __shared__ float sbuf[8 * 9 * 132];       // [pix][kk][128ci + 4 pad]
    int tid  = threadIdx.x;
    int warp = tid >> 5, lane = tid & 31;
    int m0 = blockIdx.x << 3;                 // 8 pixels per block
    int m  = m0 + warp;
    int b = m >> 12, pix = m & 4095;

    int    base[9];
    float4 wq[9];
#pragma unroll
    for (int kk = 0; kk < 9; kk++) {
        float4 par = g_par[(b * 9 + kk) * HW + pix];
        float py = par.x, px = par.y, msk = par.z;
        float y0f = floorf(py), x0f = floorf(px);
        float wy = py - y0f, wx = px - x0f;
        int y0 = (int)y0f, x0 = (int)x0f;

        int yT = min(max(y0, 0), H - 2);
        int xL = min(max(x0, 0), W - 2);
        float wyt = (yT == y0) ? (1.f - wy) : ((yT == y0 + 1) ? wy : 0.f);
        float wyb = (yT + 1 == y0) ? (1.f - wy) : ((yT == y0) ? wy : 0.f);
        float wxl = (xL == x0) ? (1.f - wx) : ((xL == x0 + 1) ? wx : 0.f);
        float wxr = (xL + 1 == x0) ? (1.f - wx) : ((xL == x0) ? wx : 0.f);
        wyt *= msk; wyb *= msk;

        base[kk] = yT * W + xL;
        wq[kk] = make_float4(wyt * wxl, wyt * wxr, wyb * wxl, wyb * wxr);
    }

    const float* xTb = g_xT + (size_t)b * HW * CI;
    float4* sb4 = (float4*)sbuf;

    for (int half = 0; half < 2; half++) {
        int ci0 = (half << 7) + (lane << 2);
#pragma unroll
        for (int kk = 0; kk < 9; kk++) {
            const float* p00 = xTb + (size_t)base[kk] * CI + ci0;
            float4 a  = *(const float4*)(p00);
            float4 bq = *(const float4*)(p00 + CI);
            float4 c  = *(const float4*)(p00 + W * CI);
            float4 d  = *(const float4*)(p00 + (W + 1) * CI);
            float4 wv = wq[kk];
            float4 v;
            v.x = tf32_rna(wv.x * a.x + wv.y * bq.x + wv.z * c.x + wv.w * d.x);
            v.y = tf32_rna(wv.x * a.y + wv.y * bq.y + wv.z * c.y + wv.w * d.y);
            v.z = tf32_rna(wv.x * a.z + wv.y * bq.z + wv.z * c.z + wv.w * d.z);
            v.w = tf32_rna(wv.x * a.w + wv.y * bq.w + wv.z * c.w + wv.w * d.w);
            sb4[(warp * 9 + kk) * 33 + lane] = v;
        }
        __syncthreads();
#pragma unroll
        for (int t = 0; t < 9; t++) {
            int i  = tid + (t << 8);
            int pw = i / 288;
            int p0 = (i - pw * 288) << 2;
            float4 v;
#pragma unroll
            for (int j = 0; j < 4; j++) {
                int kl  = p8inv(p0 + j);
                int cil = kl / 9;
                int kk  = kl - cil * 9;
                ((float*)&v)[j] = sbuf[(pw * 9 + kk) * 132 + cil];
            }
            *(float4*)&g_valA[(size_t)(m0 + pw) * KDIM + half * 1152 + p0] = v;
        }
        __syncthreads();
    }
}

// ============ Phase C: mma.sync tf32 GEMM + bias/BN-shift/ReLU ==============
// Block: M=128, N=256, KC=32; 512 threads = 16 warps as 4(m) x 4(n);
// warp tile m32 x n64 -> acc[2][8][4]. 4-buffer / depth-3 cp.async pipeline
// (R12-proven ordering: FILL first, then wait -> 4 groups in flight at wait).
#define KC     32
#define NSTG   72                 // 2304/32
#define SSTR   36                 // smem row stride (floats)
#define ASZ    (128 * SSTR)
#define BSZ    (256 * SSTR)
#define NBUF   4
#define DSMEM  ((ASZ + BSZ) * NBUF * 4)

__global__ __launch_bounds__(512, 1) void gemm_kernel(
    const float* __restrict__ bias,  const float* __restrict__ gamma,
    const float* __restrict__ beta,  const float* __restrict__ mean,
    const float* __restrict__ var,   float* __restrict__ out)
{
    extern __shared__ float dynf[];
    __shared__ float s_delta[CO];

    int tid  = threadIdx.x;
    int wid  = tid >> 5, lane = tid & 31;
    int gid  = lane >> 2, q = lane & 3;
    int wm   = wid & 3, wn = wid >> 2;

    float* As[NBUF];
    float* Bs[NBUF];
#pragma unroll
    for (int i = 0; i < NBUF; i++) {
        As[i] = dynf + i * (ASZ + BSZ);
        Bs[i] = As[i] + ASZ;
    }

    if (tid < 256) {
        float alpha = gamma[tid] * rsqrtf(var[tid] + EPSV);
        s_delta[tid] = fmaf(bias[tid] - mean[tid], alpha, beta[tid]);
    }

    int m0 = blockIdx.x << 7;

    float acc[2][8][4];
#pragma unroll
    for (int ma = 0; ma < 2; ma++)
#pragma unroll
        for (int na = 0; na < 8; na++)
#pragma unroll
            for (int e = 0; e < 4; e++) acc[ma][na][e] = 0.f;

#define FILL(sidx, buf) do {                                                   \
    const int k0 = (sidx) * KC;                                                \
    _Pragma("unroll")                                                          \
    for (int t = 0; t < 2; t++) {                                              \
        int idx4 = tid + (t << 9);                                             \
        int r = idx4 >> 3, c = idx4 & 7;                                       \
        cp_async16(smem_u32(&As[buf][r * SSTR + (c << 2)]),                    \
                   &g_valA[(size_t)(m0 + r) * KDIM + k0 + (c << 2)]);          \
    }                                                                          \
    _Pragma("unroll")                                                          \
    for (int t = 0; t < 4; t++) {                                              \
        int idx4 = tid + (t << 9);                                             \
        int r = idx4 >> 3, c = idx4 & 7;                                       \
        cp_async16(smem_u32(&Bs[buf][r * SSTR + (c << 2)]),                    \
                   &g_wB[r * KDIM + k0 + (c << 2)]);                           \
    }                                                                          \
} while (0)

    FILL(0, 0); CP_COMMIT();
    FILL(1, 1); CP_COMMIT();
    FILL(2, 2); CP_COMMIT();

    for (int s = 0; s < NSTG; s++) {
        int buf = s % NBUF;
        if (s + 3 < NSTG) {
            FILL(s + 3, (s + 3) % NBUF);   // writes buf (s-1)%NBUF: safe, see
        }                                   // trailing __syncthreads below
        CP_COMMIT();               // uniform group count (empty near tail)
        CP_WAIT3();                // oldest group (stage s) complete
        __syncthreads();

        const float* Ab = As[buf];
        const float* Bb = Bs[buf];
#pragma unroll
        for (int j = 0; j < 4; j++) {
            uint32_t af[2][4];
#pragma unroll
            for (int ma = 0; ma < 2; ma++) {
                int r0 = wm * 32 + ma * 16 + gid;
                float2 v0 = *(const float2*)&Ab[r0 * SSTR + j * 8 + q * 2];
                float2 v1 = *(const float2*)&Ab[(r0 + 8) * SSTR + j * 8 + q * 2];
                af[ma][0] = __float_as_uint(v0.x);
                af[ma][1] = __float_as_uint(v1.x);
                af[ma][2] = __float_as_uint(v0.y);
                af[ma][3] = __float_as_uint(v1.y);
            }
#pragma unroll
            for (int na = 0; na < 8; na++) {
                int n = wn * 64 + na * 8 + gid;
                float2 bv = *(const float2*)&Bb[n * SSTR + j * 8 + q * 2];
                uint32_t b0 = __float_as_uint(bv.x);
                uint32_t b1 = __float_as_uint(bv.y);
#pragma unroll
                for (int ma = 0; ma < 2; ma++)
                    mma_tf32(acc[ma][na][0], acc[ma][na][1], acc[ma][na][2], acc[ma][na][3],
                             af[ma][0], af[ma][1], af[ma][2], af[ma][3], b0, b1);
            }
        }
        __syncthreads();           // buffer reuse safety for next FILL
    }

    // ---- epilogue ----
    int b   = m0 >> 12;
    int hw0 = m0 & 4095;
    float* ob = out + b * (CO * HW);
#pragma unroll
    for (int ma = 0; ma < 2; ma++) {
#pragma unroll
        for (int na = 0; na < 8; na++) {
#pragma unroll
            for (int e = 0; e < 4; e++) {
                int row = wm * 32 + ma * 16 + gid + ((e >> 1) << 3);
                int co  = wn * 64 + na * 8 + (q << 1) + (e & 1);
                float v = acc[ma][na][e] + s_delta[co];
                ob[co * HW + hw0 + row] = fmaxf(v, 0.f);
            }
        }
    }
}

// ===========================================================================
extern "C" void kernel_launch(void* const* d_in, const int* in_sizes, int n_in,
                              void* d_out, int out_size)
{
    const float* x     = (const float*)d_in[0];
    const float* w_off = (const float*)d_in[1];
    const float* b_off = (const float*)d_in[2];
    const float* w     = (const float*)d_in[3];
    const float* bias  = (const float*)d_in[4];
    const float* gamma = (const float*)d_in[5];
    const float* beta  = (const float*)d_in[6];
    const float* mean  = (const float*)d_in[7];
    const float* var   = (const float*)d_in[8];
    float* out = (float*)d_out;

    cudaFuncSetAttribute(gemm_kernel, cudaFuncAttributeMaxDynamicSharedMemorySize, DSMEM);

    transpose_kernel<<<dim3(128, 8, 8), 256>>>(x);
    offset_kernel<<<dim3(16, 8, 4), 256>>>(x, w_off);
    reduce_kernel<<<M_TOT / 256, 256>>>(b_off);
    wt_kernel<<<CO, 256>>>(w, gamma, var);
    sample_kernel<<<M_TOT / 8, 256>>>();
    gemm_kernel<<<M_TOT / 128, 512, DSMEM>>>(bias, gamma, beta, mean, var, out);
}

// round 15
// speedup vs baseline: 1.5382x; 1.5382x over previous
#include <cuda_runtime.h>
#include <math.h>
#include <stdint.h>

#define BATCH 8
#define CI    256
#define CO    256
#define H     64
#define W     64
#define HW    4096
#define M_TOT 32768          // BATCH*HW
#define KDIM  2304           // CI*9
#define EPSV  1e-5f

// ---------------- scratch (__device__ globals: allocation-free rule) -------
__device__ float  g_valA[(size_t)M_TOT * KDIM]; // [m][k perm8], tf32-rounded (302 MB)
__device__ float  g_xT[(size_t)BATCH * HW * CI];// x transposed: [b][pix][ci] (134 MB)
__device__ float  g_om[108 * M_TOT];            // offset-conv partials [chunk*27+oc][m]
__device__ float4 g_par[BATCH * 9 * HW];        // (py, px, mask, -) per (b,kk,pixel)
__device__ float  g_wB[CO * KDIM];              // [co][k perm8], w*bn_scale, tf32-rounded

// k-permutation within 8-blocks: layout [k0,k4,k1,k5,k2,k6,k3,k7]
__device__ __forceinline__ int p8inv(int p) {
    return (p & ~7) + ((p & 7) >> 1) + ((p & 1) << 2);
}

// ===================== small helpers ========================================
__device__ __forceinline__ uint32_t smem_u32(const void* p) {
    uint32_t a;
    asm("{ .reg .u64 t; cvta.to.shared.u64 t, %1; cvt.u32.u64 %0, t; }" : "=r"(a) : "l"(p));
    return a;
}
__device__ __forceinline__ float tf32_rna(float v) {
    uint32_t u;
    asm("cvt.rna.tf32.f32 %0, %1;" : "=r"(u) : "f"(v));
    return __uint_as_float(u);
}
__device__ __forceinline__ void cp_async16(uint32_t dst, const void* src) {
    asm volatile("cp.async.cg.shared.global [%0], [%1], 16;" :: "r"(dst), "l"(src) : "memory");
}
#define CP_COMMIT() asm volatile("cp.async.commit_group;" ::: "memory")
#define CP_WAIT2()  asm volatile("cp.async.wait_group 2;" ::: "memory")

__device__ __forceinline__ unsigned long long ffma2(
    unsigned long long a, unsigned long long b, unsigned long long c)
{
    unsigned long long d;
    asm("fma.rn.f32x2 %0, %1, %2, %3;" : "=l"(d) : "l"(a), "l"(b), "l"(c));
    return d;
}
__device__ __forceinline__ unsigned long long bcast2(float v)
{
    unsigned long long d;
    asm("mov.b64 %0, {%1, %1};" : "=l"(d) : "r"(__float_as_uint(v)));
    return d;
}

__device__ __forceinline__ void mma_tf32(float& c0, float& c1, float& c2, float& c3,
                                         uint32_t a0, uint32_t a1, uint32_t a2, uint32_t a3,
                                         uint32_t b0, uint32_t b1) {
    asm volatile(
        "mma.sync.aligned.m16n8k8.row.col.f32.tf32.tf32.f32 "
        "{%0,%1,%2,%3}, {%4,%5,%6,%7}, {%8,%9}, {%0,%1,%2,%3};"
        : "+f"(c0), "+f"(c1), "+f"(c2), "+f"(c3)
        : "r"(a0), "r"(a1), "r"(a2), "r"(a3), "r"(b0), "r"(b1));
}

// ============ Phase T: NCHW -> NHWC transpose (x -> g_xT) ===================
__global__ __launch_bounds__(256) void transpose_kernel(const float* __restrict__ x)
{
    __shared__ float s[32][33];
    int b    = blockIdx.z;
    int ci0  = blockIdx.y << 5;
    int pix0 = blockIdx.x << 5;
    int tid = threadIdx.x;
    int r = tid >> 5, c = tid & 31;

    const float* xb = x + (size_t)b * CI * HW;
#pragma unroll
    for (int rr = 0; rr < 4; rr++) {
        int ci = ci0 + r + (rr << 3);
        s[r + (rr << 3)][c] = xb[(size_t)ci * HW + pix0 + c];
    }
    __syncthreads();
    float* xT = g_xT + (size_t)b * HW * CI;
#pragma unroll
    for (int rr = 0; rr < 4; rr++) {
        int pix = pix0 + r + (rr << 3);
        xT[(size_t)pix * CI + ci0 + c] = s[c][r + (rr << 3)];
    }
}

// ============ Phase A1: offset conv partials (4-way ci split, f32x2) ========
__global__ __launch_bounds__(256) void offset_kernel(
    const float* __restrict__ x, const float* __restrict__ w_off)
{
    __shared__ float xs[18 * 18];
    __shared__ __align__(8) float ws[9 * 28];  // [j][oc padded to 28]

    int b     = blockIdx.y;
    int chunk = blockIdx.z;                    // ci chunk of 64
    int tile  = blockIdx.x;                    // 16 tiles of 16x16
    int h0 = (tile >> 2) << 4;
    int w0 = (tile & 3) << 4;
    int tid = threadIdx.x;
    int ty = tid >> 4, tx = tid & 15;
    int h = h0 + ty, ww = w0 + tx;

    unsigned long long acc2[14];
#pragma unroll
    for (int i = 0; i < 14; i++) acc2[i] = 0ULL;

    const float* xb = x + b * (CI * HW);
    int ci0 = chunk << 6;
    for (int cit = 0; cit < 64; cit++) {
        int ci = ci0 + cit;
        __syncthreads();
        for (int i = tid; i < 324; i += 256) {
            int r = i / 18, c = i - r * 18;
            int gy = h0 + r - 1, gx = w0 + c - 1;
            float v = 0.f;
            if (gy >= 0 && gy < H && gx >= 0 && gx < W)
                v = xb[ci * HW + gy * W + gx];
            xs[i] = v;
        }
        if (tid < 252) {                       // 9*28 = 252
            int j = tid / 28, oc = tid - j * 28;
            ws[tid] = (oc < 27) ? w_off[oc * KDIM + ci * 9 + j] : 0.f;
        }
        __syncthreads();

        float xv[9];
#pragma unroll
        for (int ky = 0; ky < 3; ky++)
#pragma unroll
            for (int kx = 0; kx < 3; kx++)
                xv[ky * 3 + kx] = xs[(ty + ky) * 18 + tx + kx];

#pragma unroll
        for (int j = 0; j < 9; j++) {
            unsigned long long xj = bcast2(xv[j]);
            const unsigned long long* wp = (const unsigned long long*)&ws[j * 28];
#pragma unroll
            for (int p = 0; p < 14; p++)
                acc2[p] = ffma2(wp[p], xj, acc2[p]);
        }
    }

    int m = b * HW + h * W + ww;
#pragma unroll
    for (int p = 0; p < 14; p++) {
        unsigned long long v = acc2[p];
        float lo = __uint_as_float((unsigned int)(v & 0xffffffffu));
        float hi = __uint_as_float((unsigned int)(v >> 32));
        int oc = p * 2;
        g_om[(chunk * 27 + oc) * M_TOT + m] = lo;
        if (oc + 1 < 27)
            g_om[(chunk * 27 + oc + 1) * M_TOT + m] = hi;
    }
}

// ============ Phase A2: reduce partials -> bilinear params ==================
__global__ __launch_bounds__(256) void reduce_kernel(const float* __restrict__ b_off)
{
    int m = blockIdx.x * 256 + threadIdx.x;
    int b = m >> 12, pix = m & 4095;
    int h = pix >> 6, ww = pix & 63;

    float om[27];
#pragma unroll
    for (int oc = 0; oc < 27; oc++) {
        float s = b_off[oc];
#pragma unroll
        for (int c = 0; c < 4; c++)
            s += g_om[(c * 27 + oc) * M_TOT + m];
        om[oc] = s;
    }
#pragma unroll
    for (int kk = 0; kk < 9; kk++) {
        float msk = 1.f / (1.f + __expf(-om[18 + kk]));
        float py = (float)(h  + (kk / 3) - 1) + om[kk];
        float px = (float)(ww + (kk % 3) - 1) + om[9 + kk];
        g_par[(b * 9 + kk) * HW + pix] = make_float4(py, px, msk, 0.f);
    }
}

// ======= Phase W: scaled weights, perm8-laid-out =============================
__global__ void wt_kernel(const float* __restrict__ w,
                          const float* __restrict__ gamma,
                          const float* __restrict__ var)
{
    int co = blockIdx.x;
    float alpha = gamma[co] * rsqrtf(var[co] + EPSV);
    for (int k = threadIdx.x; k < KDIM; k += 256) {
        int pos = (k & ~7) + ((k & 3) << 1) + ((k & 7) >> 2);
        g_wB[co * KDIM + pos] = tf32_rna(w[co * KDIM + k] * alpha);
    }
}

// ============ Phase B: bilinear sampling (NHWC) -> g_valA[m][k perm8] =======
__global__ __launch_bounds__(256) void sample_kernel()
{
    __shared__ float sbuf[8 * 9 * 132];       // [pix][kk][128ci + 4 pad]
    int tid  = threadIdx.x;
    int warp = tid >> 5, lane = tid & 31;
    int m0 = blockIdx.x << 3;                 // 8 pixels per block
    int m  = m0 + warp;
    int b = m >> 12, pix = m & 4095;

    int    base[9];
    float4 wq[9];
#pragma unroll
    for (int kk = 0; kk < 9; kk++) {
        float4 par = g_par[(b * 9 + kk) * HW + pix];
        float py = par.x, px = par.y, msk = par.z;
        float y0f = floorf(py), x0f = floorf(px);
        float wy = py - y0f, wx = px - x0f;
        int y0 = (int)y0f, x0 = (int)x0f;

        int yT = min(max(y0, 0), H - 2);
        int xL = min(max(x0, 0), W - 2);
        float wyt = (yT == y0) ? (1.f - wy) : ((yT == y0 + 1) ? wy : 0.f);
        float wyb = (yT + 1 == y0) ? (1.f - wy) : ((yT == y0) ? wy : 0.f);
        float wxl = (xL == x0) ? (1.f - wx) : ((xL == x0 + 1) ? wx : 0.f);
        float wxr = (xL + 1 == x0) ? (1.f - wx) : ((xL == x0) ? wx : 0.f);
        wyt *= msk; wyb *= msk;

        base[kk] = yT * W + xL;
        wq[kk] = make_float4(wyt * wxl, wyt * wxr, wyb * wxl, wyb * wxr);
    }

    const float* xTb = g_xT + (size_t)b * HW * CI;
    float4* sb4 = (float4*)sbuf;

    for (int half = 0; half < 2; half++) {
        int ci0 = (half << 7) + (lane << 2);
#pragma unroll
        for (int kk = 0; kk < 9; kk++) {
            const float* p00 = xTb + (size_t)base[kk] * CI + ci0;
            float4 a  = *(const float4*)(p00);
            float4 bq = *(const float4*)(p00 + CI);
            float4 c  = *(const float4*)(p00 + W * CI);
            float4 d  = *(const float4*)(p00 + (W + 1) * CI);
            float4 wv = wq[kk];
            float4 v;
            v.x = tf32_rna(wv.x * a.x + wv.y * bq.x + wv.z * c.x + wv.w * d.x);
            v.y = tf32_rna(wv.x * a.y + wv.y * bq.y + wv.z * c.y + wv.w * d.y);
            v.z = tf32_rna(wv.x * a.z + wv.y * bq.z + wv.z * c.z + wv.w * d.z);
            v.w = tf32_rna(wv.x * a.w + wv.y * bq.w + wv.z * c.w + wv.w * d.w);
            sb4[(warp * 9 + kk) * 33 + lane] = v;
        }
        __syncthreads();
#pragma unroll
        for (int t = 0; t < 9; t++) {
            int i  = tid + (t << 8);
            int pw = i / 288;
            int p0 = (i - pw * 288) << 2;
            float4 v;
#pragma unroll
            for (int j = 0; j < 4; j++) {
                int kl  = p8inv(p0 + j);
                int cil = kl / 9;
                int kk  = kl - cil * 9;
                ((float*)&v)[j] = sbuf[(pw * 9 + kk) * 132 + cil];
            }
            *(float4*)&g_valA[(size_t)(m0 + pw) * KDIM + half * 1152 + p0] = v;
        }
        __syncthreads();
    }
}

// ============ Phase C: mma.sync tf32 GEMM + bias/BN-shift/ReLU ==============
// EXACT 693-us configuration (R12 bench): M=128, N=256, KC=32; 512 threads =
// 16 warps as 4(m) x 4(n); warp tile m32 x n64; 3-buffer cp.async pipeline.
#define KC     32
#define NSTG   72                 // 2304/32
#define SSTR   36                 // smem row stride (floats)
#define ASZ    (128 * SSTR)
#define BSZ    (256 * SSTR)
#define NBUF   3
#define DSMEM  ((ASZ + BSZ) * NBUF * 4)

__global__ __launch_bounds__(512, 1) void gemm_kernel(
    const float* __restrict__ bias,  const float* __restrict__ gamma,
    const float* __restrict__ beta,  const float* __restrict__ mean,
    const float* __restrict__ var,   float* __restrict__ out)
{
    extern __shared__ float dynf[];
    __shared__ float s_delta[CO];

    int tid  = threadIdx.x;
    int wid  = tid >> 5, lane = tid & 31;
    int gid  = lane >> 2, q = lane & 3;
    int wm   = wid & 3, wn = wid >> 2;

    float* As[NBUF];
    float* Bs[NBUF];
#pragma unroll
    for (int i = 0; i < NBUF; i++) {
        As[i] = dynf + i * (ASZ + BSZ);
        Bs[i] = As[i] + ASZ;
    }

    if (tid < 256) {
        float alpha = gamma[tid] * rsqrtf(var[tid] + EPSV);
        s_delta[tid] = fmaf(bias[tid] - mean[tid], alpha, beta[tid]);
    }

    int m0 = blockIdx.x << 7;

    float acc[2][8][4];
#pragma unroll
    for (int ma = 0; ma < 2; ma++)
#pragma unroll
        for (int na = 0; na < 8; na++)
#pragma unroll
            for (int e = 0; e < 4; e++) acc[ma][na][e] = 0.f;

#define FILL(sidx, buf) do {                                                   \
    const int k0 = (sidx) * KC;                                                \
    _Pragma("unroll")                                                          \
    for (int t = 0; t < 2; t++) {                                              \
        int idx4 = tid + (t << 9);                                             \
        int r = idx4 >> 3, c = idx4 & 7;                                       \
        cp_async16(smem_u32(&As[buf][r * SSTR + (c << 2)]),                    \
                   &g_valA[(size_t)(m0 + r) * KDIM + k0 + (c << 2)]);          \
    }                                                                          \
    _Pragma("unroll")                                                          \
    for (int t = 0; t < 4; t++) {                                              \
        int idx4 = tid + (t << 9);                                             \
        int r = idx4 >> 3, c = idx4 & 7;                                       \
        cp_async16(smem_u32(&Bs[buf][r * SSTR + (c << 2)]),                    \
                   &g_wB[r * KDIM + k0 + (c << 2)]);                           \
    }                                                                          \
} while (0)

    FILL(0, 0); CP_COMMIT();
    FILL(1, 1); CP_COMMIT();

    for (int s = 0; s < NSTG; s++) {
        int buf = s % NBUF;
        if (s + 2 < NSTG) {
            int nb = (s + 2) % NBUF;
            FILL(s + 2, nb);
        }
        CP_COMMIT();               // uniform group count (may be empty at tail)
        CP_WAIT2();                // oldest group (stage s) complete
        __syncthreads();

        const float* Ab = As[buf];
        const float* Bb = Bs[buf];
#pragma unroll
        for (int j = 0; j < 4; j++) {
            uint32_t af[2][4];
#pragma unroll
            for (int ma = 0; ma < 2; ma++) {
                int r0 = wm * 32 + ma * 16 + gid;
                float2 v0 = *(const float2*)&Ab[r0 * SSTR + j * 8 + q * 2];
                float2 v1 = *(const float2*)&Ab[(r0 + 8) * SSTR + j * 8 + q * 2];
                af[ma][0] = __float_as_uint(v0.x);
                af[ma][1] = __float_as_uint(v1.x);
                af[ma][2] = __float_as_uint(v0.y);
                af[ma][3] = __float_as_uint(v1.y);
            }
#pragma unroll
            for (int na = 0; na < 8; na++) {
                int n = wn * 64 + na * 8 + gid;
                float2 bv = *(const float2*)&Bb[n * SSTR + j * 8 + q * 2];
                uint32_t b0 = __float_as_uint(bv.x);
                uint32_t b1 = __float_as_uint(bv.y);
#pragma unroll
                for (int ma = 0; ma < 2; ma++)
                    mma_tf32(acc[ma][na][0], acc[ma][na][1], acc[ma][na][2], acc[ma][na][3],
                             af[ma][0], af[ma][1], af[ma][2], af[ma][3], b0, b1);
            }
        }
        __syncthreads();           // buffer reuse safety for next FILL
    }

    // ---- epilogue ----
    int b   = m0 >> 12;
    int hw0 = m0 & 4095;
    float* ob = out + b * (CO * HW);
#pragma unroll
    for (int ma = 0; ma < 2; ma++) {
#pragma unroll
        for (int na = 0; na < 8; na++) {
#pragma unroll
            for (int e = 0; e < 4; e++) {
                int row = wm * 32 + ma * 16 + gid + ((e >> 1) << 3);
                int co  = wn * 64 + na * 8 + (q << 1) + (e & 1);
                float v = acc[ma][na][e] + s_delta[co];
                ob[co * HW + hw0 + row] = fmaxf(v, 0.f);
            }
        }
    }
}

// ===========================================================================
extern "C" void kernel_launch(void* const* d_in, const int* in_sizes, int n_in,
                              void* d_out, int out_size)
{
    const float* x     = (const float*)d_in[0];
    const float* w_off = (const float*)d_in[1];
    const float* b_off = (const float*)d_in[2];
    const float* w     = (const float*)d_in[3];
    const float* bias  = (const float*)d_in[4];
    const float* gamma = (const float*)d_in[5];
    const float* beta  = (const float*)d_in[6];
    const float* mean  = (const float*)d_in[7];
    const float* var   = (const float*)d_in[8];
    float* out = (float*)d_out;

    cudaFuncSetAttribute(gemm_kernel, cudaFuncAttributeMaxDynamicSharedMemorySize, DSMEM);

    transpose_kernel<<<dim3(128, 8, 8), 256>>>(x);
    offset_kernel<<<dim3(16, 8, 4), 256>>>(x, w_off);
    reduce_kernel<<<M_TOT / 256, 256>>>(b_off);
    wt_kernel<<<CO, 256>>>(w, gamma, var);
    sample_kernel<<<M_TOT / 8, 256>>>();
    gemm_kernel<<<M_TOT / 128, 512, DSMEM>>>(bias, gamma, beta, mean, var, out);
}